// round 6
// baseline (speedup 1.0000x reference)
#include <cuda_runtime.h>

typedef unsigned long long u64;

#define B_    1024
#define C_    200
#define HW_   225
#define F_    12
#define FR_   6
#define NELEM (C_*HW_)   /* 45000 */
#define BT    4          /* batches per K1 block */
#define CCH   8          /* channels per staged chunk */
#define NCHK  (C_/CCH)   /* 25 chunks */

// ---------------- scratch (static device arrays; no allocation) -------------
__device__ float      g_pp  [B_*C_];    // p[b][c] - mean_c(p[b])
__device__ float2     g_an  [B_*HW_];   // {a*rs, rs} per (b,n)
__device__ float4     g_ctab[C_];       // {ln_g, (d-md)*ln_g, ln_b, 0}
__device__ ulonglong2 g_wpk [C_][9];    // packed weights (staging for const)

__constant__ ulonglong2 c_wpk[C_][9];   // weights in constant bank (28.8 KB)

// ---------------- packed-f32 helpers ---------------------------------------
__device__ __forceinline__ u64 pk2(float lo, float hi){
    u64 r; asm("mov.b64 %0, {%1,%2};" : "=l"(r) : "f"(lo), "f"(hi)); return r;
}
__device__ __forceinline__ void upk2(u64 v, float &lo, float &hi){
    asm("mov.b64 {%0,%1}, %2;" : "=f"(lo), "=f"(hi) : "l"(v));
}
__device__ __forceinline__ u64 fma2(u64 a, u64 b, u64 c){
    u64 d; asm("fma.rn.f32x2 %0, %1, %2, %3;" : "=l"(d) : "l"(a), "l"(b), "l"(c));
    return d;
}
__device__ __forceinline__ void cpa4(unsigned dst, const float* src){
    asm volatile("cp.async.ca.shared.global [%0], [%1], 4;" :: "r"(dst), "l"(src));
}
__device__ __forceinline__ void cpa_commit(){
    asm volatile("cp.async.commit_group;" ::: "memory");
}
template<int N> __device__ __forceinline__ void cpa_wait(){
    asm volatile("cp.async.wait_group %0;" :: "n"(N) : "memory");
}

// smem layout offsets (bytes) — weights no longer in smem
#define SM_XS    0                        /* float[2][7200]= 57600 */
#define SM_VS    57600                    /* float[4][12][232] = 44544 */
#define SM_KQS   102144                   /* float[4][225] = 3600 */
#define SM_TOTAL 105744

// ============================================================================
// k_pack: build packed weight pairs in global (then D2D-copied to constant).
// ============================================================================
__global__ void k_pack(const float* __restrict__ w11,
                       const float* __restrict__ w21,
                       const float* __restrict__ w31)
{
    int idx = blockIdx.x*blockDim.x + threadIdx.x;   // 0 .. 1799
    if (idx < C_*9){
        int c = idx/9, m = idx%9;
        u64 v[2];
        #pragma unroll
        for (int t=0;t<2;t++){
            int j = 2*m + t;               // 0..17
            int role = j/6, jj = j%6;
            const float* w = (role==0) ? w11 : (role==1) ? w21 : w31;
            v[t] = pk2(w[(2*jj)*C_ + c], w[(2*jj+1)*C_ + c]);
        }
        g_wpk[c][m] = make_ulonglong2(v[0], v[1]);
    }
}

// ============================================================================
// K1: block = 4 batches. cp.async double-buffered X staging; weights from
// constant bank (broadcast-native, off the smem crossbar). Epilogue: vm
// scramble, softmax, u, p/d reductions -> g_pp, g_an; block 0 writes g_ctab.
// ============================================================================
__global__ __launch_bounds__(256, 1) void k1_kernel(
    const float* __restrict__ X,
    const float* __restrict__ b11, const float* __restrict__ b21,
    const float* __restrict__ b31,
    const float* __restrict__ w41, const float* __restrict__ b41,
    const float* __restrict__ w42, const float* __restrict__ b42,
    const float* __restrict__ ln_g, const float* __restrict__ ln_b)
{
    extern __shared__ __align__(16) unsigned char dynsm[];
    float* xs = (float*)(dynsm + SM_XS);                      // [2][7200]
    float (*v_s)[F_][232] = (float (*)[F_][232])(dynsm + SM_VS);
    float (*kqs_s)[HW_]   = (float (*)[HW_])(dynsm + SM_KQS);

    __shared__ float vm_s[BT][F_], vs_s[BT][F_], u_s[BT][FR_];
    __shared__ float wred[8][5];
    __shared__ float tot[5];
    __shared__ float sh_Vd;

    const int tid = threadIdx.x;
    const int b0  = blockIdx.x * BT;

    const unsigned xs_base = (unsigned)__cvta_generic_to_shared(xs);

    // ---- staging: chunk ch -> buffer buf -----------------------------------
    const int s_cp  = tid & 63;         // 0..63  (n stepping)
    const int bt_cp = tid >> 6;         // 0..3
    const float* xsrc_b = X + (size_t)(b0 + bt_cp)*NELEM;

    auto stage = [&](int ch, int buf){
        const float* src = xsrc_b + (ch*CCH)*HW_;
        unsigned dst0 = xs_base + (unsigned)(buf*7200 + bt_cp*HW_)*4u;
        #pragma unroll
        for (int cc=0; cc<CCH; cc++){
            #pragma unroll
            for (int r=0;r<4;r++){
                int n = s_cp + 64*r;
                if (n < HW_) cpa4(dst0 + (unsigned)(cc*900 + n)*4u, src + cc*HW_ + n);
            }
        }
        cpa_commit();
    };

    stage(0, 0);
    stage(1, 1);

    // ---- GEMM main loop ----------------------------------------------------
    const int n = (tid < HW_) ? tid : (HW_-1);

    u64 acc[BT][18];
    #pragma unroll
    for (int bt=0;bt<BT;bt++)
        #pragma unroll
        for (int j=0;j<18;j++) acc[bt][j] = 0ULL;

    #pragma unroll 1
    for (int ch=0; ch<NCHK; ch++){
        cpa_wait<1>();
        __syncthreads();                 // chunk ch visible to all threads

        const int    buf   = ch & 1;
        const float* xb    = xs + buf*7200 + n;
        const int    cbase = ch*CCH;

        #pragma unroll
        for (int cc=0; cc<CCH; cc++){
            u64 xx[BT];
            #pragma unroll
            for (int bt=0;bt<BT;bt++){
                float x = xb[cc*900 + bt*HW_];
                xx[bt] = pk2(x, x);
            }
            #pragma unroll
            for (int m=0;m<9;m++){
                ulonglong2 w2 = c_wpk[cbase+cc][m];      // ld.const.v2.u64
                #pragma unroll
                for (int bt=0;bt<BT;bt++){
                    acc[bt][2*m]   = fma2(w2.x, xx[bt], acc[bt][2*m]);
                    acc[bt][2*m+1] = fma2(w2.y, xx[bt], acc[bt][2*m+1]);
                }
            }
        }

        __syncthreads();                 // everyone done reading buf
        if (ch+2 < NCHK) stage(ch+2, buf);
    }

    // ---- epilogue: biases, kqs, store v ------------------------------------
    if (tid < HW_){
        #pragma unroll
        for (int bt=0;bt<BT;bt++){
            float kv[12], qv[12], vv[12];
            #pragma unroll
            for (int j=0;j<6;j++){
                upk2(acc[bt][j],    kv[2*j], kv[2*j+1]);
                upk2(acc[bt][6+j],  qv[2*j], qv[2*j+1]);
                upk2(acc[bt][12+j], vv[2*j], vv[2*j+1]);
            }
            float kqs = 0.f;
            #pragma unroll
            for (int f=0; f<12; f++){
                float kf = kv[f] + b11[f];
                float qf = qv[f] + b21[f];
                kqs = fmaf(kf, qf, kqs);
                v_s[bt][f][n] = vv[f] + b31[f];
            }
            kqs_s[bt][n] = kqs;
        }
    }
    __syncthreads();

    // ---- vm: scrambled-reshape mean (matches reference raw reshape) --------
    if (tid < BT*F_){
        int bt = tid / F_, j = tid % F_;
        float s = 0.f;
        for (int m=0;m<HW_;m++){
            int flat = j*HW_ + m;
            int fc   = flat % 12;
            int r180 = flat % 180;
            int nn   = (flat/180)*15 + (r180/12);
            s += v_s[bt][fc][nn];
        }
        vm_s[bt][j] = s * (1.0f/HW_);
    }
    __syncthreads();

    // ---- softmax over f=12, one thread per batch ---------------------------
    if (tid < BT){
        int bt = tid;
        float mx = vm_s[bt][0];
        #pragma unroll
        for (int j=1;j<12;j++) mx = fmaxf(mx, vm_s[bt][j]);
        float e[12], ssum = 0.f;
        #pragma unroll
        for (int j=0;j<12;j++){ e[j] = __expf(vm_s[bt][j]-mx); ssum += e[j]; }
        float inv = 1.0f/ssum;
        #pragma unroll
        for (int j=0;j<12;j++) vs_s[bt][j] = e[j]*inv;
    }
    __syncthreads();

    // ---- u[bt][i] = sum_l vs[bt][l] * w41[i,l] -----------------------------
    if (tid < BT*FR_){
        int bt = tid / FR_, i = tid % FR_;
        float u = 0.f;
        #pragma unroll
        for (int l=0;l<12;l++) u = fmaf(vs_s[bt][l], w41[i*12+l], u);
        u_s[bt][i] = u;
    }
    __syncthreads();

    // ---- per-batch: p[c], d[c], reductions, then g_pp / g_an ---------------
    float Vd = 0.f;
    for (int bt=0;bt<BT;bt++){
        float p = 0.f, d = 0.f;
        if (tid < C_){
            #pragma unroll
            for (int i=0;i<6;i++){
                float wv = w42[tid*6+i];
                p = fmaf(u_s[bt][i], wv, p);
                d = fmaf(b41[i],     wv, d);
            }
            d += b42[tid];
        }
        float s0 = p, s1 = p*p, s2 = p*d, s3 = d, s4 = d*d;
        #pragma unroll
        for (int o=16;o>0;o>>=1){
            s0 += __shfl_down_sync(0xffffffffu, s0, o);
            s1 += __shfl_down_sync(0xffffffffu, s1, o);
            s2 += __shfl_down_sync(0xffffffffu, s2, o);
            s3 += __shfl_down_sync(0xffffffffu, s3, o);
            s4 += __shfl_down_sync(0xffffffffu, s4, o);
        }
        int wid = tid >> 5;
        if ((tid & 31) == 0){
            wred[wid][0]=s0; wred[wid][1]=s1; wred[wid][2]=s2; wred[wid][3]=s3; wred[wid][4]=s4;
        }
        __syncthreads();
        if (tid == 0){
            float t0=0,t1=0,t2=0,t3=0,t4=0;
            #pragma unroll
            for (int w=0;w<8;w++){ t0+=wred[w][0]; t1+=wred[w][1]; t2+=wred[w][2]; t3+=wred[w][3]; t4+=wred[w][4]; }
            tot[0]=t0; tot[1]=t1; tot[2]=t2; tot[3]=t3; tot[4]=t4;
            if (bt == 0){
                float mdd = t3*(1.0f/C_);
                sh_Vd = t4*(1.0f/C_) - mdd*mdd;
            }
        }
        __syncthreads();
        if (bt == 0) Vd = sh_Vd;
        float mp  = tot[0]*(1.0f/C_);
        float md  = tot[3]*(1.0f/C_);
        float Vp  = tot[1]*(1.0f/C_) - mp*mp;
        float Cpd = tot[2]*(1.0f/C_) - mp*md;
        if (tid < C_){
            g_pp[(b0+bt)*C_ + tid] = p - mp;
            if (bt == 0 && blockIdx.x == 0){
                float g = ln_g[tid];
                g_ctab[tid] = make_float4(g, (d - md)*g, ln_b[tid], 0.f);
            }
        }
        if (tid < HW_){
            float a   = kqs_s[bt][tid];
            float var = fmaf(a, fmaf(a, Vp, 2.0f*Cpd), Vd) + 1e-5f;
            float rs  = rsqrtf(var);
            g_an[(b0+bt)*HW_ + tid] = make_float2(a*rs, rs);
        }
        __syncthreads();
    }
}

// ============================================================================
// K2: block per batch, float4-vectorized elementwise from smem tables.
// out = x / (1 + exp(-relu(a*rs*A + rs*B + E)))
// ============================================================================
__global__ __launch_bounds__(256, 6) void k2_kernel(
    const float* __restrict__ X, float* __restrict__ out)
{
    __shared__ float4 cdat[C_];          // {pp*g, (d-md)*g, ln_b, 0}
    __shared__ float2 ans[HW_+3];        // {a*rs, rs}

    const int tid = threadIdx.x;
    const int b   = blockIdx.x;

    if (tid < C_){
        float  pp = g_pp[b*C_ + tid];
        float4 ct = g_ctab[tid];
        cdat[tid] = make_float4(pp*ct.x, ct.y, ct.z, 0.f);
    }
    if (tid < HW_) ans[tid] = g_an[b*HW_ + tid];
    __syncthreads();

    const float4* xb4 = (const float4*)(X   + (size_t)b*NELEM);
    float4*       ob4 = (float4*)      (out + (size_t)b*NELEM);

    #pragma unroll 2
    for (int i4 = tid; i4 < NELEM/4; i4 += 256){
        float4 xv = __ldcs(xb4 + i4);
        int idx = 4*i4;
        unsigned c = (unsigned)idx / 225u;
        unsigned n = (unsigned)idx - 225u*c;
        float xa[4] = {xv.x, xv.y, xv.z, xv.w};
        float ra[4];
        #pragma unroll
        for (int e=0;e<4;e++){
            float4 cd = cdat[c];
            float2 an = ans[n];
            float t = fmaf(an.x, cd.x, fmaf(an.y, cd.y, cd.z));
            t = fmaxf(t, 0.f);
            float ex = __expf(-t);
            ra[e] = __fdividef(xa[e], 1.0f + ex);
            if (++n == 225u){ n = 0u; c++; }
        }
        float4 rv = make_float4(ra[0], ra[1], ra[2], ra[3]);
        __stcs(ob4 + i4, rv);
    }
}

// ============================================================================
extern "C" void kernel_launch(void* const* d_in, const int* in_sizes, int n_in,
                              void* d_out, int out_size)
{
    const float* X    = (const float*)d_in[0];
    const float* w11  = (const float*)d_in[1];
    const float* b11  = (const float*)d_in[2];
    const float* w21  = (const float*)d_in[3];
    const float* b21  = (const float*)d_in[4];
    const float* w31  = (const float*)d_in[5];
    const float* b31  = (const float*)d_in[6];
    const float* w41  = (const float*)d_in[7];
    const float* b41  = (const float*)d_in[8];
    const float* w42  = (const float*)d_in[9];
    const float* b42  = (const float*)d_in[10];
    const float* ln_g = (const float*)d_in[11];
    const float* ln_b = (const float*)d_in[12];
    float* out = (float*)d_out;

    cudaFuncSetAttribute(k1_kernel, cudaFuncAttributeMaxDynamicSharedMemorySize, SM_TOTAL);

    // pack weights -> global, then D2D into the constant bank (capturable)
    k_pack<<<8, 256>>>(w11, w21, w31);
    void* wsrc = nullptr;
    cudaGetSymbolAddress(&wsrc, g_wpk);
    cudaMemcpyToSymbolAsync(c_wpk, wsrc, sizeof(ulonglong2)*C_*9, 0,
                            cudaMemcpyDeviceToDevice, 0);

    k1_kernel<<<B_/BT, 256, SM_TOTAL>>>(X, b11, b21, b31,
                                        w41, b41, w42, b42, ln_g, ln_b);
    k2_kernel<<<B_, 256>>>(X, out);
}

// round 7
// speedup vs baseline: 1.2531x; 1.2531x over previous
#include <cuda_runtime.h>

typedef unsigned long long u64;

#define B_    1024
#define C_    200
#define HW_   225
#define F_    12
#define FR_   6
#define NELEM (C_*HW_)   /* 45000 */
#define BT    4          /* batches per K1 block */
#define CCH   8          /* channels per staged chunk */
#define NCHK  (C_/CCH)   /* 25 chunks */
#define NBUF  4          /* pipeline depth */

// ---------------- scratch (static device arrays; no allocation) -------------
__device__ float  g_pp  [B_*C_];    // p[b][c] - mean_c(p[b])
__device__ float2 g_an  [B_*HW_];   // {a*rs, rs} per (b,n)
__device__ float4 g_ctab[C_];       // {ln_g, (d-md)*ln_g, ln_b, 0}

// ---------------- packed-f32 helpers ---------------------------------------
__device__ __forceinline__ u64 pk2(float lo, float hi){
    u64 r; asm("mov.b64 %0, {%1,%2};" : "=l"(r) : "f"(lo), "f"(hi)); return r;
}
__device__ __forceinline__ void upk2(u64 v, float &lo, float &hi){
    asm("mov.b64 {%0,%1}, %2;" : "=f"(lo), "=f"(hi) : "l"(v));
}
__device__ __forceinline__ u64 fma2(u64 a, u64 b, u64 c){
    u64 d; asm("fma.rn.f32x2 %0, %1, %2, %3;" : "=l"(d) : "l"(a), "l"(b), "l"(c));
    return d;
}
__device__ __forceinline__ void cpa16(unsigned dst, const float* src){
    asm volatile("cp.async.cg.shared.global [%0], [%1], 16;" :: "r"(dst), "l"(src));
}
__device__ __forceinline__ void cpa_commit(){
    asm volatile("cp.async.commit_group;" ::: "memory");
}
template<int N> __device__ __forceinline__ void cpa_wait(){
    asm volatile("cp.async.wait_group %0;" :: "n"(N) : "memory");
}

// dynamic smem layout (bytes):
//   [0, 28800)            wpk  u64[200][18]
//   [28800, 144000)       xs   float[4][7200]  (4 buffers x 28800 B)
//   v_s float[4][12][232] overlaps xs (used only after the GEMM loop)
#define SM_WPK   0
#define SM_XS    28800
#define SM_VS    28800
#define SM_TOTAL 144000

// ============================================================================
// K1: block = 4 batches. 4-deep cp.async pipeline (16B cg ops, contiguous
// chunks), weights from smem, one barrier per chunk. Epilogue: vm scramble,
// softmax, u, p/d reductions -> g_pp, g_an; block 0 writes g_ctab.
// ============================================================================
__global__ __launch_bounds__(256, 1) void k1_kernel(
    const float* __restrict__ X,
    const float* __restrict__ w11, const float* __restrict__ b11,
    const float* __restrict__ w21, const float* __restrict__ b21,
    const float* __restrict__ w31, const float* __restrict__ b31,
    const float* __restrict__ w41, const float* __restrict__ b41,
    const float* __restrict__ w42, const float* __restrict__ b42,
    const float* __restrict__ ln_g, const float* __restrict__ ln_b)
{
    extern __shared__ __align__(16) unsigned char dynsm[];
    u64*   wpk  = (u64*)(dynsm + SM_WPK);         // [200][18]
    float* xs   = (float*)(dynsm + SM_XS);        // [4][7200]
    float (*v_s)[F_][232] = (float (*)[F_][232])(dynsm + SM_VS);

    __shared__ float kqs_s[BT][HW_];
    __shared__ float vm_s[BT][F_], vs_s[BT][F_], u_s[BT][FR_];
    __shared__ float wred[8][5];
    __shared__ float tot[5];
    __shared__ float sh_Vd;

    const int tid = threadIdx.x;
    const int b0  = blockIdx.x * BT;

    const unsigned xs_base = (unsigned)__cvta_generic_to_shared(xs);

    // ---- staging: chunk ch (8 channels, contiguous 7200 B per batch) -------
    auto stage = [&](int ch, int buf){
        #pragma unroll 1
        for (int o = tid; o < 1800; o += 256){
            int bt = o / 450;
            int r  = o - 450*bt;
            const float* src = X + (size_t)(b0+bt)*NELEM + ch*(CCH*HW_) + r*4;
            unsigned dst = xs_base + (unsigned)(buf*28800 + bt*7200 + r*16);
            cpa16(dst, src);
        }
        cpa_commit();
    };

    stage(0, 0);
    stage(1, 1);
    stage(2, 2);

    // ---- pack weights into smem (LDGs overlap the cp.asyncs above) ---------
    for (int idx = tid; idx < C_*18; idx += 256){
        int c = idx/18, j = idx%18;
        int role = j/6, jj = j%6;
        const float* w = (role==0) ? w11 : (role==1) ? w21 : w31;
        wpk[c*18 + j] = pk2(w[(2*jj)*C_ + c], w[(2*jj+1)*C_ + c]);
    }

    // ---- GEMM main loop ----------------------------------------------------
    const int n = (tid < HW_) ? tid : (HW_-1);

    u64 acc[BT][18];
    #pragma unroll
    for (int bt=0;bt<BT;bt++)
        #pragma unroll
        for (int j=0;j<18;j++) acc[bt][j] = 0ULL;

    #pragma unroll 1
    for (int ch=0; ch<NCHK; ch++){
        cpa_wait<2>();
        __syncthreads();                 // chunk ch + wpk visible; prior reads done

        const int    buf = ch & 3;
        const float* xb  = xs + buf*7200 + n;
        const u64*   wr  = wpk + (ch*CCH)*18;

        #pragma unroll
        for (int cc=0; cc<CCH; cc++){
            u64 xx[BT];
            #pragma unroll
            for (int bt=0;bt<BT;bt++){
                float x = xb[bt*1800 + cc*HW_];
                xx[bt] = pk2(x, x);
            }
            #pragma unroll
            for (int m=0;m<9;m++){
                ulonglong2 w2 = *reinterpret_cast<const ulonglong2*>(wr + cc*18 + 2*m);
                #pragma unroll
                for (int bt=0;bt<BT;bt++){
                    acc[bt][2*m]   = fma2(w2.x, xx[bt], acc[bt][2*m]);
                    acc[bt][2*m+1] = fma2(w2.y, xx[bt], acc[bt][2*m+1]);
                }
            }
        }

        if (ch+3 < NCHK) stage(ch+3, (ch+3)&3);   // overwrites buffer read at ch-1: safe
    }
    __syncthreads();     // all warps done with xs before v_s overlays it

    // ---- epilogue: biases, kqs, store v ------------------------------------
    if (tid < HW_){
        #pragma unroll
        for (int bt=0;bt<BT;bt++){
            float kv[12], qv[12], vv[12];
            #pragma unroll
            for (int j=0;j<6;j++){
                upk2(acc[bt][j],    kv[2*j], kv[2*j+1]);
                upk2(acc[bt][6+j],  qv[2*j], qv[2*j+1]);
                upk2(acc[bt][12+j], vv[2*j], vv[2*j+1]);
            }
            float kqs = 0.f;
            #pragma unroll
            for (int f=0; f<12; f++){
                float kf = kv[f] + b11[f];
                float qf = qv[f] + b21[f];
                kqs = fmaf(kf, qf, kqs);
                v_s[bt][f][n] = vv[f] + b31[f];
            }
            kqs_s[bt][n] = kqs;
        }
    }
    __syncthreads();

    // ---- vm: scrambled-reshape mean (matches reference raw reshape) --------
    if (tid < BT*F_){
        int bt = tid / F_, j = tid % F_;
        float s = 0.f;
        for (int m=0;m<HW_;m++){
            int flat = j*HW_ + m;
            int fc   = flat % 12;
            int r180 = flat % 180;
            int nn   = (flat/180)*15 + (r180/12);
            s += v_s[bt][fc][nn];
        }
        vm_s[bt][j] = s * (1.0f/HW_);
    }
    __syncthreads();

    // ---- softmax over f=12, one thread per batch ---------------------------
    if (tid < BT){
        int bt = tid;
        float mx = vm_s[bt][0];
        #pragma unroll
        for (int j=1;j<12;j++) mx = fmaxf(mx, vm_s[bt][j]);
        float e[12], ssum = 0.f;
        #pragma unroll
        for (int j=0;j<12;j++){ e[j] = __expf(vm_s[bt][j]-mx); ssum += e[j]; }
        float inv = 1.0f/ssum;
        #pragma unroll
        for (int j=0;j<12;j++) vs_s[bt][j] = e[j]*inv;
    }
    __syncthreads();

    // ---- u[bt][i] = sum_l vs[bt][l] * w41[i,l] -----------------------------
    if (tid < BT*FR_){
        int bt = tid / FR_, i = tid % FR_;
        float u = 0.f;
        #pragma unroll
        for (int l=0;l<12;l++) u = fmaf(vs_s[bt][l], w41[i*12+l], u);
        u_s[bt][i] = u;
    }
    __syncthreads();

    // ---- per-batch: p[c], d[c], reductions, then g_pp / g_an ---------------
    float Vd = 0.f;
    for (int bt=0;bt<BT;bt++){
        float p = 0.f, d = 0.f;
        if (tid < C_){
            #pragma unroll
            for (int i=0;i<6;i++){
                float wv = w42[tid*6+i];
                p = fmaf(u_s[bt][i], wv, p);
                d = fmaf(b41[i],     wv, d);
            }
            d += b42[tid];
        }
        float s0 = p, s1 = p*p, s2 = p*d, s3 = d, s4 = d*d;
        #pragma unroll
        for (int o=16;o>0;o>>=1){
            s0 += __shfl_down_sync(0xffffffffu, s0, o);
            s1 += __shfl_down_sync(0xffffffffu, s1, o);
            s2 += __shfl_down_sync(0xffffffffu, s2, o);
            s3 += __shfl_down_sync(0xffffffffu, s3, o);
            s4 += __shfl_down_sync(0xffffffffu, s4, o);
        }
        int wid = tid >> 5;
        if ((tid & 31) == 0){
            wred[wid][0]=s0; wred[wid][1]=s1; wred[wid][2]=s2; wred[wid][3]=s3; wred[wid][4]=s4;
        }
        __syncthreads();
        if (tid == 0){
            float t0=0,t1=0,t2=0,t3=0,t4=0;
            #pragma unroll
            for (int w=0;w<8;w++){ t0+=wred[w][0]; t1+=wred[w][1]; t2+=wred[w][2]; t3+=wred[w][3]; t4+=wred[w][4]; }
            tot[0]=t0; tot[1]=t1; tot[2]=t2; tot[3]=t3; tot[4]=t4;
            if (bt == 0){
                float mdd = t3*(1.0f/C_);
                sh_Vd = t4*(1.0f/C_) - mdd*mdd;
            }
        }
        __syncthreads();
        if (bt == 0) Vd = sh_Vd;
        float mp  = tot[0]*(1.0f/C_);
        float md  = tot[3]*(1.0f/C_);
        float Vp  = tot[1]*(1.0f/C_) - mp*mp;
        float Cpd = tot[2]*(1.0f/C_) - mp*md;
        if (tid < C_){
            g_pp[(b0+bt)*C_ + tid] = p - mp;
            if (bt == 0 && blockIdx.x == 0){
                float g = ln_g[tid];
                g_ctab[tid] = make_float4(g, (d - md)*g, ln_b[tid], 0.f);
            }
        }
        if (tid < HW_){
            float a   = kqs_s[bt][tid];
            float var = fmaf(a, fmaf(a, Vp, 2.0f*Cpd), Vd) + 1e-5f;
            float rs  = rsqrtf(var);
            g_an[(b0+bt)*HW_ + tid] = make_float2(a*rs, rs);
        }
        __syncthreads();
    }
}

// ============================================================================
// K2: block per batch; thread-per-n, loop over c (coalesced rows), unroll 4.
// out = x / (1 + exp(-relu(an.x*A + an.y*B + E)))
// ============================================================================
__global__ __launch_bounds__(256, 8) void k2_kernel(
    const float* __restrict__ X, float* __restrict__ out)
{
    __shared__ float4 cdat[C_];          // {pp*g, (d-md)*g, ln_b, 0}

    const int tid = threadIdx.x;
    const int b   = blockIdx.x;

    if (tid < C_){
        float  pp = g_pp[b*C_ + tid];
        float4 ct = g_ctab[tid];
        cdat[tid] = make_float4(pp*ct.x, ct.y, ct.z, 0.f);
    }
    __syncthreads();

    if (tid < HW_){
        float2 an = g_an[b*HW_ + tid];
        const float* xp = X   + (size_t)b*NELEM + tid;
        float*       op = out + (size_t)b*NELEM + tid;
        #pragma unroll 1
        for (int c=0; c<C_; c+=4){
            float x0 = xp[0*HW_], x1 = xp[1*HW_], x2 = xp[2*HW_], x3 = xp[3*HW_];
            float4 c0 = cdat[c], c1 = cdat[c+1], c2 = cdat[c+2], c3 = cdat[c+3];
            float t0 = fmaf(an.x, c0.x, fmaf(an.y, c0.y, c0.z));
            float t1 = fmaf(an.x, c1.x, fmaf(an.y, c1.y, c1.z));
            float t2 = fmaf(an.x, c2.x, fmaf(an.y, c2.y, c2.z));
            float t3 = fmaf(an.x, c3.x, fmaf(an.y, c3.y, c3.z));
            t0 = fmaxf(t0, 0.f); t1 = fmaxf(t1, 0.f);
            t2 = fmaxf(t2, 0.f); t3 = fmaxf(t3, 0.f);
            float e0 = __expf(-t0), e1 = __expf(-t1);
            float e2 = __expf(-t2), e3 = __expf(-t3);
            op[0*HW_] = __fdividef(x0, 1.0f + e0);
            op[1*HW_] = __fdividef(x1, 1.0f + e1);
            op[2*HW_] = __fdividef(x2, 1.0f + e2);
            op[3*HW_] = __fdividef(x3, 1.0f + e3);
            xp += 4*HW_; op += 4*HW_;
        }
    }
}

// dummy: keeps the launch count at 3/call so ncu's captured slot lands on K1
__global__ void k_tail(){ }

// ============================================================================
extern "C" void kernel_launch(void* const* d_in, const int* in_sizes, int n_in,
                              void* d_out, int out_size)
{
    const float* X    = (const float*)d_in[0];
    const float* w11  = (const float*)d_in[1];
    const float* b11  = (const float*)d_in[2];
    const float* w21  = (const float*)d_in[3];
    const float* b21  = (const float*)d_in[4];
    const float* w31  = (const float*)d_in[5];
    const float* b31  = (const float*)d_in[6];
    const float* w41  = (const float*)d_in[7];
    const float* b41  = (const float*)d_in[8];
    const float* w42  = (const float*)d_in[9];
    const float* b42  = (const float*)d_in[10];
    const float* ln_g = (const float*)d_in[11];
    const float* ln_b = (const float*)d_in[12];
    float* out = (float*)d_out;

    cudaFuncSetAttribute(k1_kernel, cudaFuncAttributeMaxDynamicSharedMemorySize, SM_TOTAL);

    k1_kernel<<<B_/BT, 256, SM_TOTAL>>>(X, w11,b11, w21,b21, w31,b31,
                                        w41,b41, w42,b42, ln_g, ln_b);
    k2_kernel<<<B_, 256>>>(X, out);
    k_tail<<<1, 32>>>();
}